// round 6
// baseline (speedup 1.0000x reference)
#include <cuda_runtime.h>
#include <cuda_bf16.h>
#include <cstdint>
#include <math.h>

// Problem constants
#define BB 2
#define NN 2048
#define DD 768
#define HH 12
#define HD 64
#define BH (BB*HH)
#define XN (BB*NN*DD)
#define WN (DD*DD)

// bf16 hi/lo splits of inputs
__device__ __align__(16) __nv_bfloat16 g_xhi[XN], g_xlo[XN];
__device__ __align__(16) __nv_bfloat16 g_whi[3 * WN], g_wlo[3 * WN];
// bf16 hi/lo Q,K,V in [b,h,n,hd]
__device__ __align__(16) __nv_bfloat16 g_qhi[BH*NN*HD], g_qlo[BH*NN*HD];
__device__ __align__(16) __nv_bfloat16 g_khi[BH*NN*HD], g_klo[BH*NN*HD];
__device__ __align__(16) __nv_bfloat16 g_vhi[BH*NN*HD], g_vlo[BH*NN*HD];

__device__ __forceinline__ uint32_t smem_u32(const void* p) {
    uint32_t a;
    asm("{ .reg .u64 t; cvta.to.shared.u64 t, %1; cvt.u32.u64 %0, t; }" : "=r"(a) : "l"(p));
    return a;
}
__device__ __forceinline__ uint32_t pack2(float a, float b) {
    __nv_bfloat162 t = __floats2bfloat162_rn(a, b);
    return *reinterpret_cast<uint32_t*>(&t);
}
__device__ __forceinline__ void split2(float a, float b, uint32_t& hp, uint32_t& lp) {
    __nv_bfloat16 ha = __float2bfloat16_rn(a), hb = __float2bfloat16_rn(b);
    __nv_bfloat162 hh; hh.x = ha; hh.y = hb;
    hp = *reinterpret_cast<uint32_t*>(&hh);
    lp = pack2(a - __bfloat162float(ha), b - __bfloat162float(hb));
}
__device__ __forceinline__ void cpa16(uint32_t dst, const void* src) {
    asm volatile("cp.async.cg.shared.global [%0], [%1], 16;" :: "r"(dst), "l"(src) : "memory");
}
__device__ __forceinline__ void cpa_commit() {
    asm volatile("cp.async.commit_group;" ::: "memory");
}
__device__ __forceinline__ void ldmx4(uint32_t* r, uint32_t addr) {
    asm volatile("ldmatrix.sync.aligned.m8n8.x4.shared.b16 {%0,%1,%2,%3}, [%4];"
        : "=r"(r[0]), "=r"(r[1]), "=r"(r[2]), "=r"(r[3]) : "r"(addr));
}
__device__ __forceinline__ void ldmx4t(uint32_t* r, uint32_t addr) {
    asm volatile("ldmatrix.sync.aligned.m8n8.x4.trans.shared.b16 {%0,%1,%2,%3}, [%4];"
        : "=r"(r[0]), "=r"(r[1]), "=r"(r[2]), "=r"(r[3]) : "r"(addr));
}
__device__ __forceinline__ void mma16816(float* c, const uint32_t* a, uint32_t b0, uint32_t b1) {
    asm volatile("mma.sync.aligned.m16n8k16.row.col.f32.bf16.bf16.f32 "
        "{%0,%1,%2,%3}, {%4,%5,%6,%7}, {%8,%9}, {%0,%1,%2,%3};"
        : "+f"(c[0]), "+f"(c[1]), "+f"(c[2]), "+f"(c[3])
        : "r"(a[0]), "r"(a[1]), "r"(a[2]), "r"(a[3]), "r"(b0), "r"(b1));
}

// ---------------------------------------------------------------------------
// Split kernel
// ---------------------------------------------------------------------------
__global__ __launch_bounds__(256) void split_kernel(
    const float4* __restrict__ x, const float4* __restrict__ Wq,
    const float4* __restrict__ Wk, const float4* __restrict__ Wv)
{
    const int nx = XN / 4, nw = WN / 4;
    int i = blockIdx.x * 256 + threadIdx.x;
    if (i >= nx + 3 * nw) return;

    float4 v;
    __nv_bfloat16 *hd, *ld;
    if (i < nx) {
        v = x[i];
        hd = g_xhi + (size_t)i * 4; ld = g_xlo + (size_t)i * 4;
    } else {
        int j = i - nx;
        int z = j / nw, r = j - z * nw;
        const float4* w = (z == 0) ? Wq : (z == 1) ? Wk : Wv;
        v = w[r];
        hd = g_whi + (size_t)z * WN + (size_t)r * 4;
        ld = g_wlo + (size_t)z * WN + (size_t)r * 4;
    }
    uint32_t h0, l0, h1, l1;
    split2(v.x, v.y, h0, l0);
    split2(v.z, v.w, h1, l1);
    *reinterpret_cast<uint2*>(hd) = make_uint2(h0, h1);
    *reinterpret_cast<uint2*>(ld) = make_uint2(l0, l1);
}

// ---------------------------------------------------------------------------
// QKV GEMM: 8 warps, warp tile 64x32, CTA 128x128, bf16x3, 3-stage cp.async.
// ---------------------------------------------------------------------------
#define KC 32
#define SROW 40
#define TILE_B (128 * SROW * 2)
#define STAGE_B (4 * TILE_B)       // 40960
#define NCHUNK (DD / KC)           // 24
#define NSTG 3

__global__ __launch_bounds__(256) void qkv_mma_kernel()
{
    extern __shared__ char smc[];
    const uint32_t sb = smem_u32(smc);

    const int tid = threadIdx.x;
    const int w = tid >> 5, lane = tid & 31;
    const int wm = (w >> 2) * 64;
    const int wn = (w & 3) * 32;
    const int z = blockIdx.z;
    const int n0 = blockIdx.x * 128;
    const int m0 = blockIdx.y * 128;

    const __nv_bfloat16* __restrict__ Bhp = g_whi + (size_t)z * WN;
    const __nv_bfloat16* __restrict__ Blp = g_wlo + (size_t)z * WN;

    const int id0 = tid, id1 = 256 + tid;
    const int r0 = id0 >> 2, c0 = id0 & 3;
    const int r1 = id1 >> 2, c1 = id1 & 3;

    auto load_chunk = [&](int kt) {
        const int kb = kt * KC;
        const uint32_t st = sb + (kt % NSTG) * STAGE_B;
        {
            uint32_t doff = (uint32_t)(r0 * 80 + c0 * 16);
            size_t gA = (size_t)(m0 + r0) * DD + kb + c0 * 8;
            size_t gB = (size_t)(n0 + r0) * DD + kb + c0 * 8;
            cpa16(st + 0 * TILE_B + doff, g_xhi + gA);
            cpa16(st + 1 * TILE_B + doff, g_xlo + gA);
            cpa16(st + 2 * TILE_B + doff, Bhp + gB);
            cpa16(st + 3 * TILE_B + doff, Blp + gB);
        }
        {
            uint32_t doff = (uint32_t)(r1 * 80 + c1 * 16);
            size_t gA = (size_t)(m0 + r1) * DD + kb + c1 * 8;
            size_t gB = (size_t)(n0 + r1) * DD + kb + c1 * 8;
            cpa16(st + 0 * TILE_B + doff, g_xhi + gA);
            cpa16(st + 1 * TILE_B + doff, g_xlo + gA);
            cpa16(st + 2 * TILE_B + doff, Bhp + gB);
            cpa16(st + 3 * TILE_B + doff, Blp + gB);
        }
        cpa_commit();
    };

    float acc[4][4][4] = {};

    load_chunk(0);
    load_chunk(1);

    const int lrow = lane & 15;
    const int lcol = ((lane >> 4) & 1) * 8;

    for (int kt = 0; kt < NCHUNK; ++kt) {
        if (kt < NCHUNK - 1)
            asm volatile("cp.async.wait_group 1;" ::: "memory");
        else
            asm volatile("cp.async.wait_group 0;" ::: "memory");
        __syncthreads();

        // prefetch stage kt+2 (writes stage consumed at iter kt-1; sync above protects)
        if (kt + 2 < NCHUNK) load_chunk(kt + 2);

        const uint32_t st = sb + (kt % NSTG) * STAGE_B;

        #pragma unroll
        for (int ks = 0; ks < 2; ++ks) {
            const int kc = ks * 16 + lcol;
            uint32_t bh[2][4], bl[2][4];
            #pragma unroll
            for (int fp = 0; fp < 2; ++fp) {
                uint32_t off = (uint32_t)((wn + fp * 16 + lrow) * SROW + kc) * 2;
                ldmx4(bh[fp], st + 2 * TILE_B + off);
                ldmx4(bl[fp], st + 3 * TILE_B + off);
            }
            #pragma unroll
            for (int fm = 0; fm < 4; ++fm) {
                uint32_t ah[4], al[4];
                uint32_t off = (uint32_t)((wm + fm * 16 + lrow) * SROW + kc) * 2;
                ldmx4(ah, st + 0 * TILE_B + off);
                ldmx4(al, st + 1 * TILE_B + off);
                #pragma unroll
                for (int fn = 0; fn < 4; ++fn) {
                    const int p = fn >> 1, f = fn & 1;
                    mma16816(acc[fm][fn], ah, bh[p][f], bh[p][f + 2]);
                    mma16816(acc[fm][fn], ah, bl[p][f], bl[p][f + 2]);
                    mma16816(acc[fm][fn], al, bh[p][f], bh[p][f + 2]);
                }
            }
        }
    }

    // epilogue: split to bf16 hi/lo, store to [b,h,n,hd]
    __nv_bfloat16* Oh = (z == 0) ? g_qhi : (z == 1) ? g_khi : g_vhi;
    __nv_bfloat16* Ol = (z == 0) ? g_qlo : (z == 1) ? g_klo : g_vlo;
    const int trow = lane >> 2;
    const int tcol = (lane & 3) * 2;
    #pragma unroll
    for (int fm = 0; fm < 4; ++fm) {
        #pragma unroll
        for (int fn = 0; fn < 4; ++fn) {
            int o = n0 + wn + fn * 8 + tcol;
            int h = o >> 6, cb = o & 63;
            #pragma unroll
            for (int half = 0; half < 2; ++half) {
                int row = m0 + wm + fm * 16 + trow + half * 8;
                int b = row >> 11, n = row & (NN - 1);
                size_t idx = (((size_t)(b * HH + h)) * NN + n) * HD + cb;
                uint32_t hp, lp;
                split2(acc[fm][fn][half * 2], acc[fm][fn][half * 2 + 1], hp, lp);
                *reinterpret_cast<uint32_t*>(Oh + idx) = hp;
                *reinterpret_cast<uint32_t*>(Ol + idx) = lp;
            }
        }
    }
}

// ---------------------------------------------------------------------------
// Flash attention: 4 warps x M=32 rows (BLOCK_M=128), BLOCK_N=64, bf16x3.
// Q hi/lo in smem (loaded once); K/V 2-stage cp.async. 2 CTAs/SM.
// ---------------------------------------------------------------------------
#define VROW 72
#define KVTILE_B (64 * VROW * 2)    // 9216
#define KVSTAGE_B (4 * KVTILE_B)    // 36864
#define QTILE_B (128 * VROW * 2)    // 18432

__global__ __launch_bounds__(128) void flash_mma_kernel(float* __restrict__ out)
{
    extern __shared__ char smc[];
    const uint32_t sb = smem_u32(smc);
    const uint32_t sQh = sb;
    const uint32_t sQl = sb + QTILE_B;
    const uint32_t sKV = sb + 2 * QTILE_B;

    const int tid = threadIdx.x, wid = tid >> 5, lane = tid & 31;
    const int bh = blockIdx.y;
    const int qt = (int)gridDim.x - 1 - (int)blockIdx.x;   // heavy tiles first
    const int qbase = qt * 128;
    const int wm = wid * 32;

    const size_t base = (size_t)bh * NN * HD;
    const __nv_bfloat16* __restrict__ Qhp = g_qhi + base;
    const __nv_bfloat16* __restrict__ Qlp = g_qlo + base;
    const __nv_bfloat16* __restrict__ Kh = g_khi + base;
    const __nv_bfloat16* __restrict__ Kl = g_klo + base;
    const __nv_bfloat16* __restrict__ Vh = g_vhi + base;
    const __nv_bfloat16* __restrict__ Vl = g_vlo + base;

    auto load_kv = [&](int j, int stage) {
        const int kb = j * 64;
        const uint32_t st = sKV + stage * KVSTAGE_B;
        #pragma unroll
        for (int i = 0; i < 4; ++i) {
            int id = tid + i * 128;
            int r = id >> 3, c = id & 7;
            uint32_t doff = (uint32_t)(r * 144 + c * 16);
            size_t go = (size_t)(kb + r) * HD + c * 8;
            cpa16(st + 0 * KVTILE_B + doff, Kh + go);
            cpa16(st + 1 * KVTILE_B + doff, Kl + go);
            cpa16(st + 2 * KVTILE_B + doff, Vh + go);
            cpa16(st + 3 * KVTILE_B + doff, Vl + go);
        }
        cpa_commit();
    };

    // Q tile (hi+lo) into smem, joins KV group 0
    #pragma unroll
    for (int i = 0; i < 8; ++i) {
        int id = tid + i * 128;
        int r = id >> 3, c = id & 7;
        uint32_t doff = (uint32_t)(r * 144 + c * 16);
        size_t go = (size_t)(qbase + r) * HD + c * 8;
        cpa16(sQh + doff, Qhp + go);
        cpa16(sQl + doff, Qlp + go);
    }

    float o[2][8][4] = {};
    float mi[2][2], li[2][2];
    #pragma unroll
    for (int mf = 0; mf < 2; ++mf) {
        mi[mf][0] = mi[mf][1] = -1e30f;
        li[mf][0] = li[mf][1] = 0.0f;
    }

    const int ntiles = 2 * qt + 2;
    load_kv(0, 0);        // commits group containing Q + KV0
    load_kv(1, 1);

    const int lrow = lane & 15;
    const int lcol = ((lane >> 4) & 1) * 8;
    const int vrow_base = (lane & 7) + ((lane >> 3) & 1) * 8;
    const int vcol = ((lane >> 4) & 1) * 8;

    for (int j = 0; j < ntiles; ++j) {
        if (j < ntiles - 1)
            asm volatile("cp.async.wait_group 1;" ::: "memory");
        else
            asm volatile("cp.async.wait_group 0;" ::: "memory");
        __syncthreads();

        const bool active = (64 * j <= qbase + wm + 31);
        const uint32_t st = sKV + (j & 1) * KVSTAGE_B;

        if (active) {
            // ---- S = Q K^T (bf16x3), Q frags from smem ----
            float s[2][8][4] = {};
            #pragma unroll
            for (int kk = 0; kk < 4; ++kk) {
                const int kc = kk * 16 + lcol;
                uint32_t qhf[2][4], qlf[2][4];
                #pragma unroll
                for (int mf = 0; mf < 2; ++mf) {
                    uint32_t qoff = (uint32_t)((wm + mf * 16 + lrow) * VROW + kc) * 2;
                    ldmx4(qhf[mf], sQh + qoff);
                    ldmx4(qlf[mf], sQl + qoff);
                }
                #pragma unroll
                for (int np = 0; np < 4; ++np) {
                    uint32_t bkh[4], bkl[4];
                    uint32_t off = (uint32_t)((np * 16 + lrow) * VROW + kc) * 2;
                    ldmx4(bkh, st + 0 * KVTILE_B + off);
                    ldmx4(bkl, st + 1 * KVTILE_B + off);
                    #pragma unroll
                    for (int f = 0; f < 2; ++f) {
                        const int fn = np * 2 + f;
                        #pragma unroll
                        for (int mf = 0; mf < 2; ++mf) {
                            mma16816(s[mf][fn], qhf[mf], bkh[f], bkh[f + 2]);
                            mma16816(s[mf][fn], qhf[mf], bkl[f], bkl[f + 2]);
                            mma16816(s[mf][fn], qlf[mf], bkh[f], bkh[f + 2]);
                        }
                    }
                }
            }

            // ---- causal mask ----
            if (64 * j + 63 > qbase + wm) {
                #pragma unroll
                for (int mf = 0; mf < 2; ++mf) {
                    const int rg0 = qbase + wm + mf * 16 + (lane >> 2);
                    #pragma unroll
                    for (int fn = 0; fn < 8; ++fn) {
                        const int cb = j * 64 + fn * 8 + (lane & 3) * 2;
                        if (cb + 0 > rg0)     s[mf][fn][0] = -1e30f;
                        if (cb + 1 > rg0)     s[mf][fn][1] = -1e30f;
                        if (cb + 0 > rg0 + 8) s[mf][fn][2] = -1e30f;
                        if (cb + 1 > rg0 + 8) s[mf][fn][3] = -1e30f;
                    }
                }
            }

            // ---- online softmax ----
            float al[2][2];
            #pragma unroll
            for (int mf = 0; mf < 2; ++mf) {
                float m0n = mi[mf][0], m1n = mi[mf][1];
                #pragma unroll
                for (int fn = 0; fn < 8; ++fn) {
                    m0n = fmaxf(m0n, fmaxf(s[mf][fn][0], s[mf][fn][1]));
                    m1n = fmaxf(m1n, fmaxf(s[mf][fn][2], s[mf][fn][3]));
                }
                m0n = fmaxf(m0n, __shfl_xor_sync(0xffffffffu, m0n, 1));
                m0n = fmaxf(m0n, __shfl_xor_sync(0xffffffffu, m0n, 2));
                m1n = fmaxf(m1n, __shfl_xor_sync(0xffffffffu, m1n, 1));
                m1n = fmaxf(m1n, __shfl_xor_sync(0xffffffffu, m1n, 2));

                al[mf][0] = __expf(mi[mf][0] - m0n);
                al[mf][1] = __expf(mi[mf][1] - m1n);
                mi[mf][0] = m0n; mi[mf][1] = m1n;

                float rs0 = 0.0f, rs1 = 0.0f;
                #pragma unroll
                for (int fn = 0; fn < 8; ++fn) {
                    s[mf][fn][0] = __expf(s[mf][fn][0] - m0n);
                    s[mf][fn][1] = __expf(s[mf][fn][1] - m0n);
                    s[mf][fn][2] = __expf(s[mf][fn][2] - m1n);
                    s[mf][fn][3] = __expf(s[mf][fn][3] - m1n);
                    rs0 += s[mf][fn][0] + s[mf][fn][1];
                    rs1 += s[mf][fn][2] + s[mf][fn][3];
                }
                rs0 += __shfl_xor_sync(0xffffffffu, rs0, 1);
                rs0 += __shfl_xor_sync(0xffffffffu, rs0, 2);
                rs1 += __shfl_xor_sync(0xffffffffu, rs1, 1);
                rs1 += __shfl_xor_sync(0xffffffffu, rs1, 2);
                li[mf][0] = li[mf][0] * al[mf][0] + rs0;
                li[mf][1] = li[mf][1] * al[mf][1] + rs1;

                #pragma unroll
                for (int fn = 0; fn < 8; ++fn) {
                    o[mf][fn][0] *= al[mf][0]; o[mf][fn][1] *= al[mf][0];
                    o[mf][fn][2] *= al[mf][1]; o[mf][fn][3] *= al[mf][1];
                }
            }

            // ---- O += P V (bf16x3; P from registers) ----
            #pragma unroll
            for (int kk = 0; kk < 4; ++kk) {
                uint32_t ph[2][4], pl[2][4];
                #pragma unroll
                for (int mf = 0; mf < 2; ++mf) {
                    split2(s[mf][2*kk    ][0], s[mf][2*kk    ][1], ph[mf][0], pl[mf][0]);
                    split2(s[mf][2*kk    ][2], s[mf][2*kk    ][3], ph[mf][1], pl[mf][1]);
                    split2(s[mf][2*kk + 1][0], s[mf][2*kk + 1][1], ph[mf][2], pl[mf][2]);
                    split2(s[mf][2*kk + 1][2], s[mf][2*kk + 1][3], ph[mf][3], pl[mf][3]);
                }
                #pragma unroll
                for (int dp = 0; dp < 4; ++dp) {
                    const int vrow = kk * 16 + vrow_base;
                    uint32_t off = (uint32_t)(vrow * VROW + dp * 16 + vcol) * 2;
                    uint32_t vh_[4], vl_[4];
                    ldmx4t(vh_, st + 2 * KVTILE_B + off);
                    ldmx4t(vl_, st + 3 * KVTILE_B + off);
                    #pragma unroll
                    for (int mf = 0; mf < 2; ++mf) {
                        mma16816(o[mf][dp*2 + 0], ph[mf], vh_[0], vh_[1]);
                        mma16816(o[mf][dp*2 + 0], ph[mf], vl_[0], vl_[1]);
                        mma16816(o[mf][dp*2 + 0], pl[mf], vh_[0], vh_[1]);
                        mma16816(o[mf][dp*2 + 1], ph[mf], vh_[2], vh_[3]);
                        mma16816(o[mf][dp*2 + 1], ph[mf], vl_[2], vl_[3]);
                        mma16816(o[mf][dp*2 + 1], pl[mf], vh_[2], vh_[3]);
                    }
                }
            }
        }

        __syncthreads();
        if (j + 2 < ntiles) load_kv(j + 2, j & 1);
    }

    // ---- epilogue ----
    const int b = bh / HH, h = bh % HH;
    const int c0 = (lane & 3) * 2;
    #pragma unroll
    for (int mf = 0; mf < 2; ++mf) {
        const float inv0 = 1.0f / li[mf][0], inv1 = 1.0f / li[mf][1];
        const int r0 = qbase + wm + mf * 16 + (lane >> 2);
        #pragma unroll
        for (int fn = 0; fn < 8; ++fn) {
            const int col = h * HD + fn * 8 + c0;
            float* d0 = out + ((size_t)(b * NN + r0)) * DD + col;
            float* d1 = out + ((size_t)(b * NN + r0 + 8)) * DD + col;
            *reinterpret_cast<float2*>(d0) = make_float2(o[mf][fn][0] * inv0, o[mf][fn][1] * inv0);
            *reinterpret_cast<float2*>(d1) = make_float2(o[mf][fn][2] * inv1, o[mf][fn][3] * inv1);
        }
    }
}

static const int GEMM_SMEM  = NSTG * STAGE_B;                 // 122880
static const int FLASH_SMEM = 2 * QTILE_B + 2 * KVSTAGE_B;    // 110592

extern "C" void kernel_launch(void* const* d_in, const int* in_sizes, int n_in,
                              void* d_out, int out_size)
{
    const float* x  = (const float*)d_in[0];
    const float* Wq = (const float*)d_in[1];
    const float* Wk = (const float*)d_in[2];
    const float* Wv = (const float*)d_in[3];
    float* out = (float*)d_out;

    cudaFuncSetAttribute(qkv_mma_kernel, cudaFuncAttributeMaxDynamicSharedMemorySize, GEMM_SMEM);
    cudaFuncSetAttribute(flash_mma_kernel, cudaFuncAttributeMaxDynamicSharedMemorySize, FLASH_SMEM);

    int total4 = XN / 4 + 3 * (WN / 4);
    split_kernel<<<(total4 + 255) / 256, 256>>>(
        (const float4*)x, (const float4*)Wq, (const float4*)Wk, (const float4*)Wv);

    qkv_mma_kernel<<<dim3(DD / 128, (BB * NN) / 128, 3), 256, GEMM_SMEM>>>();

    flash_mma_kernel<<<dim3(NN / 128, BH), 128, FLASH_SMEM>>>(out);
}

// round 7
// speedup vs baseline: 1.1655x; 1.1655x over previous
#include <cuda_runtime.h>
#include <cuda_fp16.h>
#include <cstdint>
#include <math.h>

// Problem constants
#define BB 2
#define NN 2048
#define DD 768
#define HH 12
#define HD 64
#define BH (BB*HH)
#define XN (BB*NN*DD)
#define WN (DD*DD)

// fp16 hi/lo splits of inputs
__device__ __align__(16) __half g_xh[XN], g_xl[XN];
__device__ __align__(16) __half g_wh[3 * WN], g_wl[3 * WN];
// fp16 Q,K (hi/lo) and V (single) in [b,h,n,hd]
__device__ __align__(16) __half g_qh[BH*NN*HD], g_ql[BH*NN*HD];
__device__ __align__(16) __half g_kh[BH*NN*HD], g_kl[BH*NN*HD];
__device__ __align__(16) __half g_vh[BH*NN*HD];

__device__ __forceinline__ uint32_t smem_u32(const void* p) {
    uint32_t a;
    asm("{ .reg .u64 t; cvta.to.shared.u64 t, %1; cvt.u32.u64 %0, t; }" : "=r"(a) : "l"(p));
    return a;
}
__device__ __forceinline__ uint32_t pack2h(float a, float b) {
    __half2 t = __floats2half2_rn(a, b);
    return *reinterpret_cast<uint32_t*>(&t);
}
__device__ __forceinline__ void split2h(float a, float b, uint32_t& hp, uint32_t& lp) {
    __half ha = __float2half_rn(a), hb = __float2half_rn(b);
    __half2 hh = __halves2half2(ha, hb);
    hp = *reinterpret_cast<uint32_t*>(&hh);
    lp = pack2h(a - __half2float(ha), b - __half2float(hb));
}
__device__ __forceinline__ void cpa16(uint32_t dst, const void* src) {
    asm volatile("cp.async.cg.shared.global [%0], [%1], 16;" :: "r"(dst), "l"(src) : "memory");
}
__device__ __forceinline__ void cpa_commit() {
    asm volatile("cp.async.commit_group;" ::: "memory");
}
__device__ __forceinline__ void ldmx4(uint32_t* r, uint32_t addr) {
    asm volatile("ldmatrix.sync.aligned.m8n8.x4.shared.b16 {%0,%1,%2,%3}, [%4];"
        : "=r"(r[0]), "=r"(r[1]), "=r"(r[2]), "=r"(r[3]) : "r"(addr));
}
__device__ __forceinline__ void ldmx4t(uint32_t* r, uint32_t addr) {
    asm volatile("ldmatrix.sync.aligned.m8n8.x4.trans.shared.b16 {%0,%1,%2,%3}, [%4];"
        : "=r"(r[0]), "=r"(r[1]), "=r"(r[2]), "=r"(r[3]) : "r"(addr));
}
__device__ __forceinline__ void mma16816(float* c, const uint32_t* a, uint32_t b0, uint32_t b1) {
    asm volatile("mma.sync.aligned.m16n8k16.row.col.f32.f16.f16.f32 "
        "{%0,%1,%2,%3}, {%4,%5,%6,%7}, {%8,%9}, {%0,%1,%2,%3};"
        : "+f"(c[0]), "+f"(c[1]), "+f"(c[2]), "+f"(c[3])
        : "r"(a[0]), "r"(a[1]), "r"(a[2]), "r"(a[3]), "r"(b0), "r"(b1));
}

// ---------------------------------------------------------------------------
// Split kernel: fp32 -> fp16 hi + lo residual
// ---------------------------------------------------------------------------
__global__ __launch_bounds__(256) void split_kernel(
    const float4* __restrict__ x, const float4* __restrict__ Wq,
    const float4* __restrict__ Wk, const float4* __restrict__ Wv)
{
    const int nx = XN / 4, nw = WN / 4;
    int i = blockIdx.x * 256 + threadIdx.x;
    if (i >= nx + 3 * nw) return;

    float4 v;
    __half *hd, *ld;
    if (i < nx) {
        v = x[i];
        hd = g_xh + (size_t)i * 4; ld = g_xl + (size_t)i * 4;
    } else {
        int j = i - nx;
        int z = j / nw, r = j - z * nw;
        const float4* w = (z == 0) ? Wq : (z == 1) ? Wk : Wv;
        v = w[r];
        hd = g_wh + (size_t)z * WN + (size_t)r * 4;
        ld = g_wl + (size_t)z * WN + (size_t)r * 4;
    }
    uint32_t h0, l0, h1, l1;
    split2h(v.x, v.y, h0, l0);
    split2h(v.z, v.w, h1, l1);
    *reinterpret_cast<uint2*>(hd) = make_uint2(h0, h1);
    *reinterpret_cast<uint2*>(ld) = make_uint2(l0, l1);
}

// ---------------------------------------------------------------------------
// Q/K projection: 4 warps, warp tile 64x64, CTA 128x128, fp16 3-term, 2-stage.
// ---------------------------------------------------------------------------
#define KC 32
#define SROW 40
#define TILE_B (128 * SROW * 2)    // 10240
#define QK_STAGE_B (4 * TILE_B)    // 40960
#define NCHUNK (DD / KC)           // 24

__global__ __launch_bounds__(128) void qk_mma_kernel()
{
    extern __shared__ char smc[];
    const uint32_t sb = smem_u32(smc);

    const int tid = threadIdx.x;
    const int w = tid >> 5, lane = tid & 31;
    const int wm = (w >> 1) * 64;
    const int wn = (w & 1) * 64;
    const int z = blockIdx.z;                // 0=Q, 1=K
    const int n0 = blockIdx.x * 128;
    const int m0 = blockIdx.y * 128;

    const __half* __restrict__ Bhp = g_wh + (size_t)z * WN;
    const __half* __restrict__ Blp = g_wl + (size_t)z * WN;

    auto load_chunk = [&](int kt, int stage) {
        const int kb = kt * KC;
        const uint32_t st = sb + stage * QK_STAGE_B;
        #pragma unroll
        for (int i = 0; i < 4; ++i) {
            int id = tid + i * 128;
            int r = id >> 2, c = id & 3;
            uint32_t doff = (uint32_t)(r * 80 + c * 16);
            size_t gA = (size_t)(m0 + r) * DD + kb + c * 8;
            size_t gB = (size_t)(n0 + r) * DD + kb + c * 8;
            cpa16(st + 0 * TILE_B + doff, g_xh + gA);
            cpa16(st + 1 * TILE_B + doff, g_xl + gA);
            cpa16(st + 2 * TILE_B + doff, Bhp + gB);
            cpa16(st + 3 * TILE_B + doff, Blp + gB);
        }
        cpa_commit();
    };

    float acc[4][8][4] = {};

    load_chunk(0, 0);
    load_chunk(1, 1);

    const int lrow = lane & 15;
    const int lcol = ((lane >> 4) & 1) * 8;

    for (int kt = 0; kt < NCHUNK; ++kt) {
        if (kt < NCHUNK - 1)
            asm volatile("cp.async.wait_group 1;" ::: "memory");
        else
            asm volatile("cp.async.wait_group 0;" ::: "memory");
        __syncthreads();

        const uint32_t st = sb + (kt & 1) * QK_STAGE_B;

        #pragma unroll
        for (int ks = 0; ks < 2; ++ks) {
            const int kc = ks * 16 + lcol;
            uint32_t bh[4][4], bl[4][4];
            #pragma unroll
            for (int fp = 0; fp < 4; ++fp) {
                uint32_t off = (uint32_t)((wn + fp * 16 + lrow) * SROW + kc) * 2;
                ldmx4(bh[fp], st + 2 * TILE_B + off);
                ldmx4(bl[fp], st + 3 * TILE_B + off);
            }
            #pragma unroll
            for (int fm = 0; fm < 4; ++fm) {
                uint32_t ah[4], al[4];
                uint32_t off = (uint32_t)((wm + fm * 16 + lrow) * SROW + kc) * 2;
                ldmx4(ah, st + 0 * TILE_B + off);
                ldmx4(al, st + 1 * TILE_B + off);
                #pragma unroll
                for (int fn = 0; fn < 8; ++fn) {
                    const int p = fn >> 1, f = fn & 1;
                    mma16816(acc[fm][fn], ah, bh[p][f], bh[p][f + 2]);
                    mma16816(acc[fm][fn], ah, bl[p][f], bl[p][f + 2]);
                    mma16816(acc[fm][fn], al, bh[p][f], bh[p][f + 2]);
                }
            }
        }
        __syncthreads();
        if (kt + 2 < NCHUNK) load_chunk(kt + 2, kt & 1);
    }

    // epilogue: split to fp16 hi/lo, store to [b,h,n,hd]
    __half* Oh = (z == 0) ? g_qh : g_kh;
    __half* Ol = (z == 0) ? g_ql : g_kl;
    const int trow = lane >> 2;
    const int tcol = (lane & 3) * 2;
    #pragma unroll
    for (int fm = 0; fm < 4; ++fm) {
        #pragma unroll
        for (int fn = 0; fn < 8; ++fn) {
            int o = n0 + wn + fn * 8 + tcol;
            int h = o >> 6, cb = o & 63;
            #pragma unroll
            for (int half = 0; half < 2; ++half) {
                int row = m0 + wm + fm * 16 + trow + half * 8;
                int b = row >> 11, n = row & (NN - 1);
                size_t idx = (((size_t)(b * HH + h)) * NN + n) * HD + cb;
                uint32_t hp, lp;
                split2h(acc[fm][fn][half * 2], acc[fm][fn][half * 2 + 1], hp, lp);
                *reinterpret_cast<uint32_t*>(Oh + idx) = hp;
                *reinterpret_cast<uint32_t*>(Ol + idx) = lp;
            }
        }
    }
}

// ---------------------------------------------------------------------------
// V projection: single-term fp16 (Xh * Wvh). Same tiling, 2 tiles/stage.
// ---------------------------------------------------------------------------
#define V_STAGE_B (2 * TILE_B)     // 20480

__global__ __launch_bounds__(128) void v_mma_kernel()
{
    extern __shared__ char smc[];
    const uint32_t sb = smem_u32(smc);

    const int tid = threadIdx.x;
    const int w = tid >> 5, lane = tid & 31;
    const int wm = (w >> 1) * 64;
    const int wn = (w & 1) * 64;
    const int n0 = blockIdx.x * 128;
    const int m0 = blockIdx.y * 128;

    const __half* __restrict__ Bhp = g_wh + (size_t)2 * WN;

    auto load_chunk = [&](int kt, int stage) {
        const int kb = kt * KC;
        const uint32_t st = sb + stage * V_STAGE_B;
        #pragma unroll
        for (int i = 0; i < 4; ++i) {
            int id = tid + i * 128;
            int r = id >> 2, c = id & 3;
            uint32_t doff = (uint32_t)(r * 80 + c * 16);
            size_t gA = (size_t)(m0 + r) * DD + kb + c * 8;
            size_t gB = (size_t)(n0 + r) * DD + kb + c * 8;
            cpa16(st + 0 * TILE_B + doff, g_xh + gA);
            cpa16(st + 1 * TILE_B + doff, Bhp + gB);
        }
        cpa_commit();
    };

    float acc[4][8][4] = {};

    load_chunk(0, 0);
    load_chunk(1, 1);

    const int lrow = lane & 15;
    const int lcol = ((lane >> 4) & 1) * 8;

    for (int kt = 0; kt < NCHUNK; ++kt) {
        if (kt < NCHUNK - 1)
            asm volatile("cp.async.wait_group 1;" ::: "memory");
        else
            asm volatile("cp.async.wait_group 0;" ::: "memory");
        __syncthreads();

        const uint32_t st = sb + (kt & 1) * V_STAGE_B;

        #pragma unroll
        for (int ks = 0; ks < 2; ++ks) {
            const int kc = ks * 16 + lcol;
            uint32_t bh[4][4];
            #pragma unroll
            for (int fp = 0; fp < 4; ++fp) {
                uint32_t off = (uint32_t)((wn + fp * 16 + lrow) * SROW + kc) * 2;
                ldmx4(bh[fp], st + 1 * TILE_B + off);
            }
            #pragma unroll
            for (int fm = 0; fm < 4; ++fm) {
                uint32_t ah[4];
                uint32_t off = (uint32_t)((wm + fm * 16 + lrow) * SROW + kc) * 2;
                ldmx4(ah, st + 0 * TILE_B + off);
                #pragma unroll
                for (int fn = 0; fn < 8; ++fn) {
                    const int p = fn >> 1, f = fn & 1;
                    mma16816(acc[fm][fn], ah, bh[p][f], bh[p][f + 2]);
                }
            }
        }
        __syncthreads();
        if (kt + 2 < NCHUNK) load_chunk(kt + 2, kt & 1);
    }

    // epilogue: single fp16 V
    const int trow = lane >> 2;
    const int tcol = (lane & 3) * 2;
    #pragma unroll
    for (int fm = 0; fm < 4; ++fm) {
        #pragma unroll
        for (int fn = 0; fn < 8; ++fn) {
            int o = n0 + wn + fn * 8 + tcol;
            int h = o >> 6, cb = o & 63;
            #pragma unroll
            for (int half = 0; half < 2; ++half) {
                int row = m0 + wm + fm * 16 + trow + half * 8;
                int b = row >> 11, n = row & (NN - 1);
                size_t idx = (((size_t)(b * HH + h)) * NN + n) * HD + cb;
                *reinterpret_cast<uint32_t*>(g_vh + idx) =
                    pack2h(acc[fm][fn][half * 2], acc[fm][fn][half * 2 + 1]);
            }
        }
    }
}

// ---------------------------------------------------------------------------
// Flash attention: 4 warps x M=32 rows (BLOCK_M=128), BLOCK_N=64.
// S = 3-term fp16; PV = single-term fp16. K hi/lo + V single per stage.
// ---------------------------------------------------------------------------
#define VROW 72
#define KVTILE_B (64 * VROW * 2)    // 9216
#define KVSTAGE_B (3 * KVTILE_B)    // 27648

__global__ __launch_bounds__(128) void flash_mma_kernel(float* __restrict__ out)
{
    extern __shared__ char smc[];
    const uint32_t sb = smem_u32(smc);
    const int tid = threadIdx.x, wid = tid >> 5, lane = tid & 31;
    const int bh = blockIdx.y;
    const int qt = (int)gridDim.x - 1 - (int)blockIdx.x;   // heavy tiles first
    const int qbase = qt * 128;
    const int wm = wid * 32;
    const int rowmax = qbase + wm + 31;

    const size_t base = (size_t)bh * NN * HD;
    const __half* __restrict__ Qhp = g_qh + base;
    const __half* __restrict__ Qlp = g_ql + base;
    const __half* __restrict__ Khp = g_kh + base;
    const __half* __restrict__ Klp = g_kl + base;
    const __half* __restrict__ Vhp = g_vh + base;

    // Q fragments in registers (2 m-frags of 16 rows)
    uint32_t qh[2][4][4], ql[2][4][4];
    {
        const int r0 = qbase + wm + (lane >> 2);
        const int c0 = (lane & 3) * 2;
        #pragma unroll
        for (int mf = 0; mf < 2; ++mf) {
            #pragma unroll
            for (int kk = 0; kk < 4; ++kk) {
                #pragma unroll
                for (int jj = 0; jj < 4; ++jj) {
                    int row = r0 + mf * 16 + (jj & 1) * 8;
                    int col = kk * 16 + c0 + (jj >> 1) * 8;
                    qh[mf][kk][jj] = *reinterpret_cast<const uint32_t*>(Qhp + (size_t)row * HD + col);
                    ql[mf][kk][jj] = *reinterpret_cast<const uint32_t*>(Qlp + (size_t)row * HD + col);
                }
            }
        }
    }

    auto load_kv = [&](int j, int stage) {
        const int kb = j * 64;
        const uint32_t st = sb + stage * KVSTAGE_B;
        #pragma unroll
        for (int i = 0; i < 4; ++i) {
            int id = tid + i * 128;
            int r = id >> 3, c = id & 7;
            uint32_t doff = (uint32_t)(r * 144 + c * 16);
            size_t go = (size_t)(kb + r) * HD + c * 8;
            cpa16(st + 0 * KVTILE_B + doff, Khp + go);
            cpa16(st + 1 * KVTILE_B + doff, Klp + go);
            cpa16(st + 2 * KVTILE_B + doff, Vhp + go);
        }
        cpa_commit();
    };

    float o[2][8][4] = {};
    float mi[2][2], li[2][2];
    #pragma unroll
    for (int mf = 0; mf < 2; ++mf) {
        mi[mf][0] = mi[mf][1] = -1e30f;
        li[mf][0] = li[mf][1] = 0.0f;
    }

    const int ntiles = 2 * qt + 2;
    load_kv(0, 0);
    if (ntiles > 1) load_kv(1, 1);

    const int lrow = lane & 15;
    const int lcol = ((lane >> 4) & 1) * 8;
    const int vrow_base = (lane & 7) + ((lane >> 3) & 1) * 8;
    const int vcol = ((lane >> 4) & 1) * 8;

    for (int j = 0; j < ntiles; ++j) {
        if (j < ntiles - 1)
            asm volatile("cp.async.wait_group 1;" ::: "memory");
        else
            asm volatile("cp.async.wait_group 0;" ::: "memory");
        __syncthreads();

        const int j64 = 64 * j;
        const bool active = (j64 <= rowmax);
        const int nlim = rowmax - j64;          // n-block valid if nb*16 <= nlim
        const uint32_t st = sb + (j & 1) * KVSTAGE_B;

        if (active) {
            // ---- S = Q K^T (fp16 3-term), skip fully-masked np blocks ----
            float s[2][8][4] = {};
            #pragma unroll
            for (int kk = 0; kk < 4; ++kk) {
                const int kc = kk * 16 + lcol;
                #pragma unroll
                for (int np = 0; np < 4; ++np) {
                    if (np * 16 <= nlim) {
                        uint32_t bkh[4], bkl[4];
                        uint32_t off = (uint32_t)((np * 16 + lrow) * VROW + kc) * 2;
                        ldmx4(bkh, st + 0 * KVTILE_B + off);
                        ldmx4(bkl, st + 1 * KVTILE_B + off);
                        #pragma unroll
                        for (int f = 0; f < 2; ++f) {
                            const int fn = np * 2 + f;
                            #pragma unroll
                            for (int mf = 0; mf < 2; ++mf) {
                                mma16816(s[mf][fn], qh[mf][kk], bkh[f], bkh[f + 2]);
                                mma16816(s[mf][fn], qh[mf][kk], bkl[f], bkl[f + 2]);
                                mma16816(s[mf][fn], ql[mf][kk], bkh[f], bkh[f + 2]);
                            }
                        }
                    }
                }
            }

            // ---- causal mask ----
            if (j64 + 63 > qbase + wm) {
                #pragma unroll
                for (int mf = 0; mf < 2; ++mf) {
                    const int rg0 = qbase + wm + mf * 16 + (lane >> 2);
                    #pragma unroll
                    for (int fn = 0; fn < 8; ++fn) {
                        const int cb = j64 + fn * 8 + (lane & 3) * 2;
                        if (cb + 0 > rg0)     s[mf][fn][0] = -1e30f;
                        if (cb + 1 > rg0)     s[mf][fn][1] = -1e30f;
                        if (cb + 0 > rg0 + 8) s[mf][fn][2] = -1e30f;
                        if (cb + 1 > rg0 + 8) s[mf][fn][3] = -1e30f;
                    }
                }
            }

            // ---- online softmax ----
            #pragma unroll
            for (int mf = 0; mf < 2; ++mf) {
                float m0n = mi[mf][0], m1n = mi[mf][1];
                #pragma unroll
                for (int fn = 0; fn < 8; ++fn) {
                    m0n = fmaxf(m0n, fmaxf(s[mf][fn][0], s[mf][fn][1]));
                    m1n = fmaxf(m1n, fmaxf(s[mf][fn][2], s[mf][fn][3]));
                }
                m0n = fmaxf(m0n, __shfl_xor_sync(0xffffffffu, m0n, 1));
                m0n = fmaxf(m0n, __shfl_xor_sync(0xffffffffu, m0n, 2));
                m1n = fmaxf(m1n, __shfl_xor_sync(0xffffffffu, m1n, 1));
                m1n = fmaxf(m1n, __shfl_xor_sync(0xffffffffu, m1n, 2));

                const float al0 = __expf(mi[mf][0] - m0n);
                const float al1 = __expf(mi[mf][1] - m1n);
                mi[mf][0] = m0n; mi[mf][1] = m1n;

                float rs0 = 0.0f, rs1 = 0.0f;
                #pragma unroll
                for (int fn = 0; fn < 8; ++fn) {
                    s[mf][fn][0] = __expf(s[mf][fn][0] - m0n);
                    s[mf][fn][1] = __expf(s[mf][fn][1] - m0n);
                    s[mf][fn][2] = __expf(s[mf][fn][2] - m1n);
                    s[mf][fn][3] = __expf(s[mf][fn][3] - m1n);
                    rs0 += s[mf][fn][0] + s[mf][fn][1];
                    rs1 += s[mf][fn][2] + s[mf][fn][3];
                }
                rs0 += __shfl_xor_sync(0xffffffffu, rs0, 1);
                rs0 += __shfl_xor_sync(0xffffffffu, rs0, 2);
                rs1 += __shfl_xor_sync(0xffffffffu, rs1, 1);
                rs1 += __shfl_xor_sync(0xffffffffu, rs1, 2);
                li[mf][0] = li[mf][0] * al0 + rs0;
                li[mf][1] = li[mf][1] * al1 + rs1;

                #pragma unroll
                for (int fn = 0; fn < 8; ++fn) {
                    o[mf][fn][0] *= al0; o[mf][fn][1] *= al0;
                    o[mf][fn][2] *= al1; o[mf][fn][3] *= al1;
                }
            }

            // ---- O += P V (single-term fp16), skip fully-masked kk blocks ----
            #pragma unroll
            for (int kk = 0; kk < 4; ++kk) {
                if (kk * 16 <= nlim) {
                    uint32_t ph[2][4];
                    #pragma unroll
                    for (int mf = 0; mf < 2; ++mf) {
                        ph[mf][0] = pack2h(s[mf][2*kk    ][0], s[mf][2*kk    ][1]);
                        ph[mf][1] = pack2h(s[mf][2*kk    ][2], s[mf][2*kk    ][3]);
                        ph[mf][2] = pack2h(s[mf][2*kk + 1][0], s[mf][2*kk + 1][1]);
                        ph[mf][3] = pack2h(s[mf][2*kk + 1][2], s[mf][2*kk + 1][3]);
                    }
                    #pragma unroll
                    for (int dp = 0; dp < 4; ++dp) {
                        const int vrow = kk * 16 + vrow_base;
                        uint32_t off = (uint32_t)(vrow * VROW + dp * 16 + vcol) * 2;
                        uint32_t vh_[4];
                        ldmx4t(vh_, st + 2 * KVTILE_B + off);
                        #pragma unroll
                        for (int mf = 0; mf < 2; ++mf) {
                            mma16816(o[mf][dp*2 + 0], ph[mf], vh_[0], vh_[1]);
                            mma16816(o[mf][dp*2 + 1], ph[mf], vh_[2], vh_[3]);
                        }
                    }
                }
            }
        }

        __syncthreads();
        if (j + 2 < ntiles) load_kv(j + 2, j & 1);
    }

    // ---- epilogue ----
    const int b = bh / HH, h = bh % HH;
    const int c0 = (lane & 3) * 2;
    #pragma unroll
    for (int mf = 0; mf < 2; ++mf) {
        const float inv0 = 1.0f / li[mf][0], inv1 = 1.0f / li[mf][1];
        const int r0 = qbase + wm + mf * 16 + (lane >> 2);
        #pragma unroll
        for (int fn = 0; fn < 8; ++fn) {
            const int col = h * HD + fn * 8 + c0;
            float* d0 = out + ((size_t)(b * NN + r0)) * DD + col;
            float* d1 = out + ((size_t)(b * NN + r0 + 8)) * DD + col;
            *reinterpret_cast<float2*>(d0) = make_float2(o[mf][fn][0] * inv0, o[mf][fn][1] * inv0);
            *reinterpret_cast<float2*>(d1) = make_float2(o[mf][fn][2] * inv1, o[mf][fn][3] * inv1);
        }
    }
}

static const int QK_SMEM    = 2 * QK_STAGE_B;   // 81920
static const int V_SMEM     = 2 * V_STAGE_B;    // 40960
static const int FLASH_SMEM = 2 * KVSTAGE_B;    // 55296

extern "C" void kernel_launch(void* const* d_in, const int* in_sizes, int n_in,
                              void* d_out, int out_size)
{
    const float* x  = (const float*)d_in[0];
    const float* Wq = (const float*)d_in[1];
    const float* Wk = (const float*)d_in[2];
    const float* Wv = (const float*)d_in[3];
    float* out = (float*)d_out;

    cudaFuncSetAttribute(qk_mma_kernel, cudaFuncAttributeMaxDynamicSharedMemorySize, QK_SMEM);
    cudaFuncSetAttribute(v_mma_kernel, cudaFuncAttributeMaxDynamicSharedMemorySize, V_SMEM);
    cudaFuncSetAttribute(flash_mma_kernel, cudaFuncAttributeMaxDynamicSharedMemorySize, FLASH_SMEM);

    int total4 = XN / 4 + 3 * (WN / 4);
    split_kernel<<<(total4 + 255) / 256, 256>>>(
        (const float4*)x, (const float4*)Wq, (const float4*)Wk, (const float4*)Wv);

    qk_mma_kernel<<<dim3(DD / 128, (BB * NN) / 128, 2), 128, QK_SMEM>>>();
    v_mma_kernel<<<dim3(DD / 128, (BB * NN) / 128), 128, V_SMEM>>>();

    flash_mma_kernel<<<dim3(NN / 128, BH), 128, FLASH_SMEM>>>(out);
}

// round 8
// speedup vs baseline: 1.2309x; 1.0561x over previous
#include <cuda_runtime.h>
#include <cuda_fp16.h>
#include <cstdint>
#include <math.h>

#define BB 2
#define NN 2048
#define DD 768
#define HH 12
#define HD 64
#define BH (BB*HH)
#define XN (BB*NN*DD)
#define WN (DD*DD)

__device__ __align__(16) __half g_xh[XN], g_xl[XN];
__device__ __align__(16) __half g_wh[3 * WN], g_wl[3 * WN];
__device__ __align__(16) __half g_qh[BH*NN*HD], g_ql[BH*NN*HD];
__device__ __align__(16) __half g_kh[BH*NN*HD], g_kl[BH*NN*HD];
__device__ __align__(16) __half g_vh[BH*NN*HD];

__device__ __forceinline__ uint32_t smem_u32(const void* p) {
    uint32_t a;
    asm("{ .reg .u64 t; cvta.to.shared.u64 t, %1; cvt.u32.u64 %0, t; }" : "=r"(a) : "l"(p));
    return a;
}
__device__ __forceinline__ uint32_t pack2h(float a, float b) {
    __half2 t = __floats2half2_rn(a, b);
    return *reinterpret_cast<uint32_t*>(&t);
}
__device__ __forceinline__ void split2h(float a, float b, uint32_t& hp, uint32_t& lp) {
    __half ha = __float2half_rn(a), hb = __float2half_rn(b);
    __half2 hh = __halves2half2(ha, hb);
    hp = *reinterpret_cast<uint32_t*>(&hh);
    lp = pack2h(a - __half2float(ha), b - __half2float(hb));
}
__device__ __forceinline__ void cpa16(uint32_t dst, const void* src) {
    asm volatile("cp.async.cg.shared.global [%0], [%1], 16;" :: "r"(dst), "l"(src) : "memory");
}
__device__ __forceinline__ void cpa_commit() {
    asm volatile("cp.async.commit_group;" ::: "memory");
}
__device__ __forceinline__ void ldmx4(uint32_t* r, uint32_t addr) {
    asm volatile("ldmatrix.sync.aligned.m8n8.x4.shared.b16 {%0,%1,%2,%3}, [%4];"
        : "=r"(r[0]), "=r"(r[1]), "=r"(r[2]), "=r"(r[3]) : "r"(addr));
}
__device__ __forceinline__ void ldmx4t(uint32_t* r, uint32_t addr) {
    asm volatile("ldmatrix.sync.aligned.m8n8.x4.trans.shared.b16 {%0,%1,%2,%3}, [%4];"
        : "=r"(r[0]), "=r"(r[1]), "=r"(r[2]), "=r"(r[3]) : "r"(addr));
}
__device__ __forceinline__ void mma16816(float* c, const uint32_t* a, uint32_t b0, uint32_t b1) {
    asm volatile("mma.sync.aligned.m16n8k16.row.col.f32.f16.f16.f32 "
        "{%0,%1,%2,%3}, {%4,%5,%6,%7}, {%8,%9}, {%0,%1,%2,%3};"
        : "+f"(c[0]), "+f"(c[1]), "+f"(c[2]), "+f"(c[3])
        : "r"(a[0]), "r"(a[1]), "r"(a[2]), "r"(a[3]), "r"(b0), "r"(b1));
}

// ---------------------------------------------------------------------------
// Split kernel
// ---------------------------------------------------------------------------
__global__ __launch_bounds__(256) void split_kernel(
    const float4* __restrict__ x, const float4* __restrict__ Wq,
    const float4* __restrict__ Wk, const float4* __restrict__ Wv)
{
    const int nx = XN / 4, nw = WN / 4;
    int i = blockIdx.x * 256 + threadIdx.x;
    if (i >= nx + 3 * nw) return;

    float4 v;
    __half *hd, *ld;
    if (i < nx) {
        v = x[i];
        hd = g_xh + (size_t)i * 4; ld = g_xl + (size_t)i * 4;
    } else {
        int j = i - nx;
        int z = j / nw, r = j - z * nw;
        const float4* w = (z == 0) ? Wq : (z == 1) ? Wk : Wv;
        v = w[r];
        hd = g_wh + (size_t)z * WN + (size_t)r * 4;
        ld = g_wl + (size_t)z * WN + (size_t)r * 4;
    }
    uint32_t h0, l0, h1, l1;
    split2h(v.x, v.y, h0, l0);
    split2h(v.z, v.w, h1, l1);
    *reinterpret_cast<uint2*>(hd) = make_uint2(h0, h1);
    *reinterpret_cast<uint2*>(ld) = make_uint2(l0, l1);
}

// ---------------------------------------------------------------------------
// Q/K projection: CTA 64(M) x 128(N), 4 warps x (32x64), fp16 3-term, 2-stage.
// ---------------------------------------------------------------------------
#define KC 32
#define SROW 40
#define A_TILE_B (64 * SROW * 2)      // 5120
#define B_TILE_B (128 * SROW * 2)     // 10240
#define QK_STAGE_B (2 * A_TILE_B + 2 * B_TILE_B)   // 30720
#define NCHUNK (DD / KC)              // 24

__global__ __launch_bounds__(128, 3) void qk_mma_kernel()
{
    extern __shared__ char smc[];
    const uint32_t sb = smem_u32(smc);

    const int tid = threadIdx.x;
    const int w = tid >> 5, lane = tid & 31;
    const int wm = (w >> 1) * 32;
    const int wn = (w & 1) * 64;
    const int z = blockIdx.z;               // 0=Q, 1=K
    const int n0 = blockIdx.x * 128;
    const int m0 = blockIdx.y * 64;

    const __half* __restrict__ Bhp = g_wh + (size_t)z * WN;
    const __half* __restrict__ Blp = g_wl + (size_t)z * WN;

    auto load_chunk = [&](int kt, int stage) {
        const int kb = kt * KC;
        const uint32_t st = sb + stage * QK_STAGE_B;
        // A hi/lo: 64 rows x 4 chunks = 256 entries
        #pragma unroll
        for (int i = 0; i < 2; ++i) {
            int id = tid + i * 128;
            int r = id >> 2, c = id & 3;
            uint32_t doff = (uint32_t)(r * 80 + c * 16);
            size_t gA = (size_t)(m0 + r) * DD + kb + c * 8;
            cpa16(st + 0 * A_TILE_B + doff, g_xh + gA);
            cpa16(st + 1 * A_TILE_B + doff, g_xl + gA);
        }
        // B hi/lo: 128 rows x 4 chunks = 512 entries
        #pragma unroll
        for (int i = 0; i < 4; ++i) {
            int id = tid + i * 128;
            int r = id >> 2, c = id & 3;
            uint32_t doff = (uint32_t)(r * 80 + c * 16);
            size_t gB = (size_t)(n0 + r) * DD + kb + c * 8;
            cpa16(st + 2 * A_TILE_B + 0 * B_TILE_B + doff, Bhp + gB);
            cpa16(st + 2 * A_TILE_B + 1 * B_TILE_B + doff, Blp + gB);
        }
        cpa_commit();
    };

    float acc[2][8][4] = {};

    load_chunk(0, 0);
    load_chunk(1, 1);

    const int lrow = lane & 15;
    const int lcol = ((lane >> 4) & 1) * 8;

    for (int kt = 0; kt < NCHUNK; ++kt) {
        if (kt < NCHUNK - 1)
            asm volatile("cp.async.wait_group 1;" ::: "memory");
        else
            asm volatile("cp.async.wait_group 0;" ::: "memory");
        __syncthreads();

        const uint32_t st = sb + (kt & 1) * QK_STAGE_B;
        const uint32_t stB = st + 2 * A_TILE_B;

        #pragma unroll
        for (int ks = 0; ks < 2; ++ks) {
            const int kc = ks * 16 + lcol;
            uint32_t bh[4][4], bl[4][4];
            #pragma unroll
            for (int fp = 0; fp < 4; ++fp) {
                uint32_t off = (uint32_t)((wn + fp * 16 + lrow) * SROW + kc) * 2;
                ldmx4(bh[fp], stB + 0 * B_TILE_B + off);
                ldmx4(bl[fp], stB + 1 * B_TILE_B + off);
            }
            #pragma unroll
            for (int mf = 0; mf < 2; ++mf) {
                uint32_t ah[4], al[4];
                uint32_t off = (uint32_t)((wm + mf * 16 + lrow) * SROW + kc) * 2;
                ldmx4(ah, st + 0 * A_TILE_B + off);
                ldmx4(al, st + 1 * A_TILE_B + off);
                #pragma unroll
                for (int fn = 0; fn < 8; ++fn) {
                    const int p = fn >> 1, f = fn & 1;
                    mma16816(acc[mf][fn], ah, bh[p][f], bh[p][f + 2]);
                    mma16816(acc[mf][fn], ah, bl[p][f], bl[p][f + 2]);
                    mma16816(acc[mf][fn], al, bh[p][f], bh[p][f + 2]);
                }
            }
        }
        __syncthreads();
        if (kt + 2 < NCHUNK) load_chunk(kt + 2, kt & 1);
    }

    __half* Oh = (z == 0) ? g_qh : g_kh;
    __half* Ol = (z == 0) ? g_ql : g_kl;
    const int trow = lane >> 2;
    const int tcol = (lane & 3) * 2;
    #pragma unroll
    for (int mf = 0; mf < 2; ++mf) {
        #pragma unroll
        for (int fn = 0; fn < 8; ++fn) {
            int o = n0 + wn + fn * 8 + tcol;
            int h = o >> 6, cb = o & 63;
            #pragma unroll
            for (int half = 0; half < 2; ++half) {
                int row = m0 + wm + mf * 16 + trow + half * 8;
                int b = row >> 11, n = row & (NN - 1);
                size_t idx = (((size_t)(b * HH + h)) * NN + n) * HD + cb;
                uint32_t hp, lp;
                split2h(acc[mf][fn][half * 2], acc[mf][fn][half * 2 + 1], hp, lp);
                *reinterpret_cast<uint32_t*>(Oh + idx) = hp;
                *reinterpret_cast<uint32_t*>(Ol + idx) = lp;
            }
        }
    }
}

// ---------------------------------------------------------------------------
// V projection: single-term fp16, CTA 64x128, 4 warps x (32x64).
// ---------------------------------------------------------------------------
#define V_STAGE_B (A_TILE_B + B_TILE_B)   // 15360

__global__ __launch_bounds__(128, 4) void v_mma_kernel()
{
    extern __shared__ char smc[];
    const uint32_t sb = smem_u32(smc);

    const int tid = threadIdx.x;
    const int w = tid >> 5, lane = tid & 31;
    const int wm = (w >> 1) * 32;
    const int wn = (w & 1) * 64;
    const int n0 = blockIdx.x * 128;
    const int m0 = blockIdx.y * 64;

    const __half* __restrict__ Bhp = g_wh + (size_t)2 * WN;

    auto load_chunk = [&](int kt, int stage) {
        const int kb = kt * KC;
        const uint32_t st = sb + stage * V_STAGE_B;
        #pragma unroll
        for (int i = 0; i < 2; ++i) {
            int id = tid + i * 128;
            int r = id >> 2, c = id & 3;
            uint32_t doff = (uint32_t)(r * 80 + c * 16);
            cpa16(st + doff, g_xh + (size_t)(m0 + r) * DD + kb + c * 8);
        }
        #pragma unroll
        for (int i = 0; i < 4; ++i) {
            int id = tid + i * 128;
            int r = id >> 2, c = id & 3;
            uint32_t doff = (uint32_t)(r * 80 + c * 16);
            cpa16(st + A_TILE_B + doff, Bhp + (size_t)(n0 + r) * DD + kb + c * 8);
        }
        cpa_commit();
    };

    float acc[2][8][4] = {};

    load_chunk(0, 0);
    load_chunk(1, 1);

    const int lrow = lane & 15;
    const int lcol = ((lane >> 4) & 1) * 8;

    for (int kt = 0; kt < NCHUNK; ++kt) {
        if (kt < NCHUNK - 1)
            asm volatile("cp.async.wait_group 1;" ::: "memory");
        else
            asm volatile("cp.async.wait_group 0;" ::: "memory");
        __syncthreads();

        const uint32_t st = sb + (kt & 1) * V_STAGE_B;

        #pragma unroll
        for (int ks = 0; ks < 2; ++ks) {
            const int kc = ks * 16 + lcol;
            uint32_t bh[4][4];
            #pragma unroll
            for (int fp = 0; fp < 4; ++fp) {
                uint32_t off = (uint32_t)((wn + fp * 16 + lrow) * SROW + kc) * 2;
                ldmx4(bh[fp], st + A_TILE_B + off);
            }
            #pragma unroll
            for (int mf = 0; mf < 2; ++mf) {
                uint32_t ah[4];
                uint32_t off = (uint32_t)((wm + mf * 16 + lrow) * SROW + kc) * 2;
                ldmx4(ah, st + off);
                #pragma unroll
                for (int fn = 0; fn < 8; ++fn) {
                    const int p = fn >> 1, f = fn & 1;
                    mma16816(acc[mf][fn], ah, bh[p][f], bh[p][f + 2]);
                }
            }
        }
        __syncthreads();
        if (kt + 2 < NCHUNK) load_chunk(kt + 2, kt & 1);
    }

    const int trow = lane >> 2;
    const int tcol = (lane & 3) * 2;
    #pragma unroll
    for (int mf = 0; mf < 2; ++mf) {
        #pragma unroll
        for (int fn = 0; fn < 8; ++fn) {
            int o = n0 + wn + fn * 8 + tcol;
            int h = o >> 6, cb = o & 63;
            #pragma unroll
            for (int half = 0; half < 2; ++half) {
                int row = m0 + wm + mf * 16 + trow + half * 8;
                int b = row >> 11, n = row & (NN - 1);
                size_t idx = (((size_t)(b * HH + h)) * NN + n) * HD + cb;
                *reinterpret_cast<uint32_t*>(g_vh + idx) =
                    pack2h(acc[mf][fn][half * 2], acc[mf][fn][half * 2 + 1]);
            }
        }
    }
}

// ---------------------------------------------------------------------------
// Flash attention: BLOCK_M=64, 4 warps x 16 rows, BLOCK_N=64.
// S 3-term fp16, PV single-term. 3 CTAs/SM.
// ---------------------------------------------------------------------------
#define VROW 72
#define KVTILE_B (64 * VROW * 2)    // 9216
#define KVSTAGE_B (3 * KVTILE_B)    // 27648

__global__ __launch_bounds__(128, 3) void flash_mma_kernel(float* __restrict__ out)
{
    extern __shared__ char smc[];
    const uint32_t sb = smem_u32(smc);
    const int tid = threadIdx.x, wid = tid >> 5, lane = tid & 31;
    const int bh = blockIdx.y;
    const int qt = (int)gridDim.x - 1 - (int)blockIdx.x;   // heavy tiles first
    const int qbase = qt * 64;
    const int wm = wid * 16;
    const int rowmax = qbase + wm + 15;

    const size_t base = (size_t)bh * NN * HD;
    const __half* __restrict__ Qhp = g_qh + base;
    const __half* __restrict__ Qlp = g_ql + base;
    const __half* __restrict__ Khp = g_kh + base;
    const __half* __restrict__ Klp = g_kl + base;
    const __half* __restrict__ Vhp = g_vh + base;

    // Q fragments (16 rows per warp)
    uint32_t qh[4][4], ql[4][4];
    {
        const int r0 = qbase + wm + (lane >> 2);
        const int c0 = (lane & 3) * 2;
        #pragma unroll
        for (int kk = 0; kk < 4; ++kk) {
            #pragma unroll
            for (int jj = 0; jj < 4; ++jj) {
                int row = r0 + (jj & 1) * 8;
                int col = kk * 16 + c0 + (jj >> 1) * 8;
                qh[kk][jj] = *reinterpret_cast<const uint32_t*>(Qhp + (size_t)row * HD + col);
                ql[kk][jj] = *reinterpret_cast<const uint32_t*>(Qlp + (size_t)row * HD + col);
            }
        }
    }

    auto load_kv = [&](int j, int stage) {
        const int kb = j * 64;
        const uint32_t st = sb + stage * KVSTAGE_B;
        #pragma unroll
        for (int i = 0; i < 4; ++i) {
            int id = tid + i * 128;
            int r = id >> 3, c = id & 7;
            uint32_t doff = (uint32_t)(r * 144 + c * 16);
            size_t go = (size_t)(kb + r) * HD + c * 8;
            cpa16(st + 0 * KVTILE_B + doff, Khp + go);
            cpa16(st + 1 * KVTILE_B + doff, Klp + go);
            cpa16(st + 2 * KVTILE_B + doff, Vhp + go);
        }
        cpa_commit();
    };

    float o[8][4] = {};
    float mi0 = -1e30f, mi1 = -1e30f, li0 = 0.0f, li1 = 0.0f;

    const int ntiles = qt + 1;
    load_kv(0, 0);
    if (ntiles > 1) load_kv(1, 1);

    const int lrow = lane & 15;
    const int lcol = ((lane >> 4) & 1) * 8;
    const int vrow_base = (lane & 7) + ((lane >> 3) & 1) * 8;
    const int vcol = ((lane >> 4) & 1) * 8;

    for (int j = 0; j < ntiles; ++j) {
        if (j < ntiles - 1)
            asm volatile("cp.async.wait_group 1;" ::: "memory");
        else
            asm volatile("cp.async.wait_group 0;" ::: "memory");
        __syncthreads();

        const int j64 = 64 * j;
        const int nlim = rowmax - j64;      // >= 15 always; np/kk block valid iff blk*16 <= nlim
        const uint32_t st = sb + (j & 1) * KVSTAGE_B;

        // ---- S = Q K^T (fp16 3-term), skip masked np blocks ----
        float s[8][4] = {};
        #pragma unroll
        for (int kk = 0; kk < 4; ++kk) {
            const int kc = kk * 16 + lcol;
            #pragma unroll
            for (int np = 0; np < 4; ++np) {
                if (np * 16 <= nlim) {
                    uint32_t bkh[4], bkl[4];
                    uint32_t off = (uint32_t)((np * 16 + lrow) * VROW + kc) * 2;
                    ldmx4(bkh, st + 0 * KVTILE_B + off);
                    ldmx4(bkl, st + 1 * KVTILE_B + off);
                    #pragma unroll
                    for (int f = 0; f < 2; ++f) {
                        const int fn = np * 2 + f;
                        mma16816(s[fn], qh[kk], bkh[f], bkh[f + 2]);
                        mma16816(s[fn], qh[kk], bkl[f], bkl[f + 2]);
                        mma16816(s[fn], ql[kk], bkh[f], bkh[f + 2]);
                    }
                }
            }
        }

        // ---- causal mask (last tile only) ----
        if (j == qt) {
            const int rg0 = qbase + wm + (lane >> 2);
            #pragma unroll
            for (int fn = 0; fn < 8; ++fn) {
                const int cb = j64 + fn * 8 + (lane & 3) * 2;
                if (cb + 0 > rg0)     s[fn][0] = -1e30f;
                if (cb + 1 > rg0)     s[fn][1] = -1e30f;
                if (cb + 0 > rg0 + 8) s[fn][2] = -1e30f;
                if (cb + 1 > rg0 + 8) s[fn][3] = -1e30f;
            }
        }

        // ---- online softmax ----
        {
            float m0n = mi0, m1n = mi1;
            #pragma unroll
            for (int fn = 0; fn < 8; ++fn) {
                m0n = fmaxf(m0n, fmaxf(s[fn][0], s[fn][1]));
                m1n = fmaxf(m1n, fmaxf(s[fn][2], s[fn][3]));
            }
            m0n = fmaxf(m0n, __shfl_xor_sync(0xffffffffu, m0n, 1));
            m0n = fmaxf(m0n, __shfl_xor_sync(0xffffffffu, m0n, 2));
            m1n = fmaxf(m1n, __shfl_xor_sync(0xffffffffu, m1n, 1));
            m1n = fmaxf(m1n, __shfl_xor_sync(0xffffffffu, m1n, 2));

            const float al0 = __expf(mi0 - m0n);
            const float al1 = __expf(mi1 - m1n);
            mi0 = m0n; mi1 = m1n;

            float rs0 = 0.0f, rs1 = 0.0f;
            #pragma unroll
            for (int fn = 0; fn < 8; ++fn) {
                s[fn][0] = __expf(s[fn][0] - m0n);
                s[fn][1] = __expf(s[fn][1] - m0n);
                s[fn][2] = __expf(s[fn][2] - m1n);
                s[fn][3] = __expf(s[fn][3] - m1n);
                rs0 += s[fn][0] + s[fn][1];
                rs1 += s[fn][2] + s[fn][3];
            }
            rs0 += __shfl_xor_sync(0xffffffffu, rs0, 1);
            rs0 += __shfl_xor_sync(0xffffffffu, rs0, 2);
            rs1 += __shfl_xor_sync(0xffffffffu, rs1, 1);
            rs1 += __shfl_xor_sync(0xffffffffu, rs1, 2);
            li0 = li0 * al0 + rs0;
            li1 = li1 * al1 + rs1;

            #pragma unroll
            for (int fn = 0; fn < 8; ++fn) {
                o[fn][0] *= al0; o[fn][1] *= al0;
                o[fn][2] *= al1; o[fn][3] *= al1;
            }
        }

        // ---- O += P V (single-term fp16), skip masked kk blocks ----
        #pragma unroll
        for (int kk = 0; kk < 4; ++kk) {
            if (kk * 16 <= nlim) {
                uint32_t ph[4];
                ph[0] = pack2h(s[2*kk    ][0], s[2*kk    ][1]);
                ph[1] = pack2h(s[2*kk    ][2], s[2*kk    ][3]);
                ph[2] = pack2h(s[2*kk + 1][0], s[2*kk + 1][1]);
                ph[3] = pack2h(s[2*kk + 1][2], s[2*kk + 1][3]);
                #pragma unroll
                for (int dp = 0; dp < 4; ++dp) {
                    const int vrow = kk * 16 + vrow_base;
                    uint32_t off = (uint32_t)(vrow * VROW + dp * 16 + vcol) * 2;
                    uint32_t vh_[4];
                    ldmx4t(vh_, st + 2 * KVTILE_B + off);
                    mma16816(o[dp*2 + 0], ph, vh_[0], vh_[1]);
                    mma16816(o[dp*2 + 1], ph, vh_[2], vh_[3]);
                }
            }
        }

        __syncthreads();
        if (j + 2 < ntiles) load_kv(j + 2, j & 1);
    }

    // ---- epilogue ----
    const int b = bh / HH, h = bh % HH;
    const float inv0 = 1.0f / li0, inv1 = 1.0f / li1;
    const int r0 = qbase + wm + (lane >> 2);
    const int c0 = (lane & 3) * 2;
    #pragma unroll
    for (int fn = 0; fn < 8; ++fn) {
        const int col = h * HD + fn * 8 + c0;
        float* d0 = out + ((size_t)(b * NN + r0)) * DD + col;
        float* d1 = out + ((size_t)(b * NN + r0 + 8)) * DD + col;
        *reinterpret_cast<float2*>(d0) = make_float2(o[fn][0] * inv0, o[fn][1] * inv0);
        *reinterpret_cast<float2*>(d1) = make_float2(o[fn][2] * inv1, o[fn][3] * inv1);
    }
}

static const int QK_SMEM    = 2 * QK_STAGE_B;   // 61440
static const int V_SMEM     = 2 * V_STAGE_B;    // 30720
static const int FLASH_SMEM = 2 * KVSTAGE_B;    // 55296

extern "C" void kernel_launch(void* const* d_in, const int* in_sizes, int n_in,
                              void* d_out, int out_size)
{
    const float* x  = (const float*)d_in[0];
    const float* Wq = (const float*)d_in[1];
    const float* Wk = (const float*)d_in[2];
    const float* Wv = (const float*)d_in[3];
    float* out = (float*)d_out;

    cudaFuncSetAttribute(qk_mma_kernel, cudaFuncAttributeMaxDynamicSharedMemorySize, QK_SMEM);
    cudaFuncSetAttribute(v_mma_kernel, cudaFuncAttributeMaxDynamicSharedMemorySize, V_SMEM);
    cudaFuncSetAttribute(flash_mma_kernel, cudaFuncAttributeMaxDynamicSharedMemorySize, FLASH_SMEM);

    int total4 = XN / 4 + 3 * (WN / 4);
    split_kernel<<<(total4 + 255) / 256, 256>>>(
        (const float4*)x, (const float4*)Wq, (const float4*)Wk, (const float4*)Wv);

    qk_mma_kernel<<<dim3(DD / 128, (BB * NN) / 64, 2), 128, QK_SMEM>>>();
    v_mma_kernel<<<dim3(DD / 128, (BB * NN) / 64), 128, V_SMEM>>>();

    flash_mma_kernel<<<dim3(NN / 64, BH), 128, FLASH_SMEM>>>(out);
}